// round 3
// baseline (speedup 1.0000x reference)
#include <cuda_runtime.h>
#include <math.h>

// Problem constants
#define HID   1024
#define NTOK  4096          // B*S = 2*2048
#define KDIM  9216          // 1024 (silu) + 1024*8 (spline bases)
#define OUT3  3072          // 3*HID qkv
#define SEQ   2048
#define BHN   32            // B*HEADS
#define DH    64
#define QT    64
#define KT    32

// ---------------- scratch (static __device__, no allocations) ----------------
__device__ __align__(16) float g_A    [(long)NTOK * KDIM];   // 151 MB
__device__ __align__(16) float g_Bmat [(long)OUT3 * KDIM];   // 113 MB
__device__ __align__(16) float g_qkv  [(long)NTOK * OUT3];   //  50 MB
__device__ __align__(16) float g_qr   [(long)BHN * SEQ * DH];
__device__ __align__(16) float g_kr   [(long)BHN * SEQ * DH];
__device__ __align__(16) float g_vg   [(long)BHN * SEQ * DH];
__device__ __align__(16) float g_ctx  [(long)NTOK * HID];

// ---------------- prep: Bmat = [base_weight | spline_weight * scaler] --------
__global__ void prep_w(const float* __restrict__ bw,
                       const float* __restrict__ sw,
                       const float* __restrict__ sc)
{
    long i = (long)blockIdx.x * 256 + threadIdx.x;   // over OUT3*HID
    if (i >= (long)OUT3 * HID) return;
    int out = (int)(i >> 10), in = (int)(i & 1023);
    float s = sc[i];
    long rb = (long)out * KDIM;
    g_Bmat[rb + in] = bw[i];
    const float4* swv = (const float4*)(sw + i * 8);
    float4 r0 = swv[0], r1 = swv[1];
    r0.x *= s; r0.y *= s; r0.z *= s; r0.w *= s;
    r1.x *= s; r1.y *= s; r1.z *= s; r1.w *= s;
    float4* dst = (float4*)(g_Bmat + rb + HID + (long)in * 8);
    dst[0] = r0; dst[1] = r1;
}

// ---------------- prep: A = [silu(x) | b_splines(x)] ------------------------
__global__ void prep_a(const float* __restrict__ x,
                       const float* __restrict__ grid)
{
    long i = (long)blockIdx.x * 256 + threadIdx.x;   // over NTOK*HID
    if (i >= (long)NTOK * HID) return;
    int n = (int)(i >> 10), in = (int)(i & 1023);
    float xv = x[i];
    long ra = (long)n * KDIM;
    // silu
    g_A[ra + in] = xv / (1.0f + expf(-xv));
    // b-splines (Cox-de Boor, k=3, 12 knots -> 8 cubic bases)
    float g[12];
#pragma unroll
    for (int t = 0; t < 12; t++) g[t] = grid[in * 12 + t];
    float bas[11];
#pragma unroll
    for (int j = 0; j < 11; j++)
        bas[j] = (xv >= g[j] && xv < g[j + 1]) ? 1.0f : 0.0f;
#pragma unroll
    for (int p = 1; p <= 3; p++) {
#pragma unroll
        for (int j = 0; j < 11 - p; j++) {
            bas[j] = (xv - g[j]) / (g[j + p] - g[j]) * bas[j]
                   + (g[j + p + 1] - xv) / (g[j + p + 1] - g[j + 1]) * bas[j + 1];
        }
    }
    float4* dst = (float4*)(g_A + ra + HID + (long)in * 8);
    dst[0] = make_float4(bas[0], bas[1], bas[2], bas[3]);
    dst[1] = make_float4(bas[4], bas[5], bas[6], bas[7]);
}

// ---------------- generic NT GEMM: C = A(MxK) * B(NxK)^T (+bias) ------------
// 128x128x16 tile, 256 threads, 8x8 per thread, double-buffered smem.
// All dims divisible by tile sizes.
__global__ void __launch_bounds__(256) gemm_nt(
    const float* __restrict__ A, const float* __restrict__ B, float* __restrict__ C,
    int K, int lda, int ldb, int ldc, const float* __restrict__ bias)
{
    const int brow = blockIdx.y * 128;
    const int bcol = blockIdx.x * 128;

    __shared__ float As[2][16][132];
    __shared__ float Bs[2][16][132];

    const int tid = threadIdx.x;
    const int tx = tid & 15;          // -> N
    const int ty = tid >> 4;          // -> M

    // loader mapping: 512 float4 per operand per tile, 2 per thread
    const int r_0  = tid >> 1;              // rows 0..127 (u=0)
    const int kq_0 = (tid & 1) * 4;         // k 0..4
    const int r_1  = r_0;                   // u=1 uses k+8
    const int kq_1 = kq_0 + 8;

    const float* Arow0 = A + (long)(brow + r_0) * lda;
    const float* Brow0 = B + (long)(bcol + r_0) * ldb;

    float acc[8][8];
#pragma unroll
    for (int i = 0; i < 8; i++)
#pragma unroll
        for (int j = 0; j < 8; j++) acc[i][j] = 0.0f;

    const int ntile = K / 16;

    // preload tile 0
    {
        float4 va0 = *(const float4*)(Arow0 + kq_0);
        float4 va1 = *(const float4*)(Arow0 + kq_1);
        float4 vb0 = *(const float4*)(Brow0 + kq_0);
        float4 vb1 = *(const float4*)(Brow0 + kq_1);
        As[0][kq_0 + 0][r_0] = va0.x; As[0][kq_0 + 1][r_0] = va0.y;
        As[0][kq_0 + 2][r_0] = va0.z; As[0][kq_0 + 3][r_0] = va0.w;
        As[0][kq_1 + 0][r_1] = va1.x; As[0][kq_1 + 1][r_1] = va1.y;
        As[0][kq_1 + 2][r_1] = va1.z; As[0][kq_1 + 3][r_1] = va1.w;
        Bs[0][kq_0 + 0][r_0] = vb0.x; Bs[0][kq_0 + 1][r_0] = vb0.y;
        Bs[0][kq_0 + 2][r_0] = vb0.z; Bs[0][kq_0 + 3][r_0] = vb0.w;
        Bs[0][kq_1 + 0][r_1] = vb1.x; Bs[0][kq_1 + 1][r_1] = vb1.y;
        Bs[0][kq_1 + 2][r_1] = vb1.z; Bs[0][kq_1 + 3][r_1] = vb1.w;
    }
    __syncthreads();

    for (int t = 0; t < ntile; t++) {
        const int cur = t & 1, nxt = cur ^ 1;
        float4 va0, va1, vb0, vb1;
        const bool more = (t + 1) < ntile;
        if (more) {
            int koff = (t + 1) * 16;
            va0 = *(const float4*)(Arow0 + koff + kq_0);
            va1 = *(const float4*)(Arow0 + koff + kq_1);
            vb0 = *(const float4*)(Brow0 + koff + kq_0);
            vb1 = *(const float4*)(Brow0 + koff + kq_1);
        }
#pragma unroll
        for (int kk = 0; kk < 16; kk++) {
            float ra[8], rb[8];
#pragma unroll
            for (int i = 0; i < 8; i++) ra[i] = As[cur][kk][ty * 8 + i];
#pragma unroll
            for (int j = 0; j < 8; j++) rb[j] = Bs[cur][kk][tx * 8 + j];
#pragma unroll
            for (int i = 0; i < 8; i++)
#pragma unroll
                for (int j = 0; j < 8; j++)
                    acc[i][j] += ra[i] * rb[j];
        }
        if (more) {
            As[nxt][kq_0 + 0][r_0] = va0.x; As[nxt][kq_0 + 1][r_0] = va0.y;
            As[nxt][kq_0 + 2][r_0] = va0.z; As[nxt][kq_0 + 3][r_0] = va0.w;
            As[nxt][kq_1 + 0][r_1] = va1.x; As[nxt][kq_1 + 1][r_1] = va1.y;
            As[nxt][kq_1 + 2][r_1] = va1.z; As[nxt][kq_1 + 3][r_1] = va1.w;
            Bs[nxt][kq_0 + 0][r_0] = vb0.x; Bs[nxt][kq_0 + 1][r_0] = vb0.y;
            Bs[nxt][kq_0 + 2][r_0] = vb0.z; Bs[nxt][kq_0 + 3][r_0] = vb0.w;
            Bs[nxt][kq_1 + 0][r_1] = vb1.x; Bs[nxt][kq_1 + 1][r_1] = vb1.y;
            Bs[nxt][kq_1 + 2][r_1] = vb1.z; Bs[nxt][kq_1 + 3][r_1] = vb1.w;
        }
        __syncthreads();
    }

#pragma unroll
    for (int i = 0; i < 8; i++) {
        long row = brow + ty * 8 + i;
#pragma unroll
        for (int j = 0; j < 8; j++) {
            int col = bcol + tx * 8 + j;
            float v = acc[i][j];
            if (bias) v += bias[col];
            C[row * ldc + col] = v;
        }
    }
}

// ---------------- rotate q,k by R (qr[m]=sum_d q[d]*R[m][d]) + copy v -------
__global__ void __launch_bounds__(256) rotqkv(const float* __restrict__ R)
{
    const int bh = blockIdx.x;
    const int s0 = blockIdx.y * 64;
    const int b = bh >> 4, h = bh & 15;
    __shared__ float RsT[64][65];     // RsT[d][m] = R[m][d]
    __shared__ float T[64][64];
    const int tid = threadIdx.x;

    for (int i = tid; i < 4096; i += 256) {
        int m = i >> 6, d = i & 63;
        RsT[d][m] = R[i];             // R row-major [m][d]
    }
    // load Q tile + copy V
    for (int i = tid; i < 4096; i += 256) {
        int t = i >> 6, d = i & 63;
        long n = (long)(b * SEQ + s0 + t);
        const float* base = g_qkv + n * OUT3 + h * 192;
        T[t][d] = base[d];
        g_vg[((long)bh * SEQ + s0 + t) * DH + d] = base[128 + d];
    }
    __syncthreads();
    for (int i = tid; i < 4096; i += 256) {
        int t = i >> 6, m = i & 63;
        float sum = 0.0f;
#pragma unroll
        for (int d = 0; d < 64; d++) sum += T[t][d] * RsT[d][m];
        g_qr[((long)bh * SEQ + s0 + t) * DH + m] = sum;
    }
    __syncthreads();
    // K tile
    for (int i = tid; i < 4096; i += 256) {
        int t = i >> 6, d = i & 63;
        long n = (long)(b * SEQ + s0 + t);
        T[t][d] = g_qkv[n * OUT3 + h * 192 + 64 + d];
    }
    __syncthreads();
    for (int i = tid; i < 4096; i += 256) {
        int t = i >> 6, m = i & 63;
        float sum = 0.0f;
#pragma unroll
        for (int d = 0; d < 64; d++) sum += T[t][d] * RsT[d][m];
        g_kr[((long)bh * SEQ + s0 + t) * DH + m] = sum;
    }
}

// ---------------- flash attention: ctx = softmax(qr krT / 8) v --------------
// One block per (64 q rows, bh). 256 threads: tx=tid&7 (cols), ty=tid>>3 (2 rows).
__global__ void __launch_bounds__(256) flash_attn()
{
    const int bh = blockIdx.y;
    const int q0 = blockIdx.x * QT;
    const int b = bh >> 4, h = bh & 15;

    __shared__ float Qst[DH][QT];      // [d][q]
    __shared__ float Kst[DH][KT];      // [d][n]
    __shared__ float Vs [KT][DH];      // [n][d]
    __shared__ float Pst[KT][QT + 2];  // [n][q]

    const int tid = threadIdx.x;
    const int tx = tid & 7;
    const int ty = tid >> 3;
    const int r0 = ty * 2, r1 = r0 + 1;

    // load Q tile transposed (1024 float4, 4 per thread)
#pragma unroll
    for (int u = 0; u < 4; u++) {
        int e = tid + u * 256;
        int q = e >> 4;
        int d4 = (e & 15) * 4;
        float4 v = *(const float4*)(g_qr + ((long)bh * SEQ + q0 + q) * DH + d4);
        Qst[d4 + 0][q] = v.x; Qst[d4 + 1][q] = v.y;
        Qst[d4 + 2][q] = v.z; Qst[d4 + 3][q] = v.w;
    }

    float m0 = -1e30f, m1 = -1e30f, l0 = 0.f, l1 = 0.f;
    float o0[8], o1[8];
#pragma unroll
    for (int u = 0; u < 8; u++) { o0[u] = 0.f; o1[u] = 0.f; }

    for (int kt = 0; kt < SEQ; kt += KT) {
        __syncthreads();
        // load K (transposed) + V tiles (512 float4 each, 2 per thread)
#pragma unroll
        for (int u = 0; u < 2; u++) {
            int e = tid + u * 256;
            int n = e >> 4;
            int d4 = (e & 15) * 4;
            float4 kv = *(const float4*)(g_kr + ((long)bh * SEQ + kt + n) * DH + d4);
            Kst[d4 + 0][n] = kv.x; Kst[d4 + 1][n] = kv.y;
            Kst[d4 + 2][n] = kv.z; Kst[d4 + 3][n] = kv.w;
            float4 vv = *(const float4*)(g_vg + ((long)bh * SEQ + kt + n) * DH + d4);
            *(float4*)&Vs[n][d4] = vv;
        }
        __syncthreads();

        // S = Q K^T (2x4 per thread)
        float s0[4], s1[4];
#pragma unroll
        for (int c = 0; c < 4; c++) { s0[c] = 0.f; s1[c] = 0.f; }
#pragma unroll 8
        for (int kk = 0; kk < DH; kk++) {
            float2 qa = *(const float2*)&Qst[kk][r0];
            float4 kb = *(const float4*)&Kst[kk][tx * 4];
            s0[0] += qa.x * kb.x; s0[1] += qa.x * kb.y;
            s0[2] += qa.x * kb.z; s0[3] += qa.x * kb.w;
            s1[0] += qa.y * kb.x; s1[1] += qa.y * kb.y;
            s1[2] += qa.y * kb.z; s1[3] += qa.y * kb.w;
        }
        float tm0 = -1e30f, tm1 = -1e30f;
#pragma unroll
        for (int c = 0; c < 4; c++) {
            s0[c] *= 0.125f; s1[c] *= 0.125f;
            tm0 = fmaxf(tm0, s0[c]); tm1 = fmaxf(tm1, s1[c]);
        }
#pragma unroll
        for (int o = 1; o < 8; o <<= 1) {
            tm0 = fmaxf(tm0, __shfl_xor_sync(0xffffffffu, tm0, o));
            tm1 = fmaxf(tm1, __shfl_xor_sync(0xffffffffu, tm1, o));
        }
        float nm0 = fmaxf(m0, tm0), nm1 = fmaxf(m1, tm1);
        float c0 = __expf(m0 - nm0), c1 = __expf(m1 - nm1);
        m0 = nm0; m1 = nm1;
        float ts0 = 0.f, ts1 = 0.f;
        float p0[4], p1[4];
#pragma unroll
        for (int c = 0; c < 4; c++) {
            p0[c] = __expf(s0[c] - nm0); ts0 += p0[c];
            p1[c] = __expf(s1[c] - nm1); ts1 += p1[c];
        }
#pragma unroll
        for (int o = 1; o < 8; o <<= 1) {
            ts0 += __shfl_xor_sync(0xffffffffu, ts0, o);
            ts1 += __shfl_xor_sync(0xffffffffu, ts1, o);
        }
        l0 = l0 * c0 + ts0;
        l1 = l1 * c1 + ts1;
#pragma unroll
        for (int u = 0; u < 8; u++) { o0[u] *= c0; o1[u] *= c1; }
#pragma unroll
        for (int c = 0; c < 4; c++) {
            Pst[tx * 4 + c][r0] = p0[c];
            Pst[tx * 4 + c][r1] = p1[c];
        }
        __syncthreads();
        // O += P V (2 rows x 8 cols per thread)
#pragma unroll 4
        for (int j = 0; j < KT; j++) {
            float2 pa = *(const float2*)&Pst[j][r0];
            float4 va = *(const float4*)&Vs[j][tx * 8];
            float4 vb = *(const float4*)&Vs[j][tx * 8 + 4];
            o0[0] += pa.x * va.x; o0[1] += pa.x * va.y;
            o0[2] += pa.x * va.z; o0[3] += pa.x * va.w;
            o0[4] += pa.x * vb.x; o0[5] += pa.x * vb.y;
            o0[6] += pa.x * vb.z; o0[7] += pa.x * vb.w;
            o1[0] += pa.y * va.x; o1[1] += pa.y * va.y;
            o1[2] += pa.y * va.z; o1[3] += pa.y * va.w;
            o1[4] += pa.y * vb.x; o1[5] += pa.y * vb.y;
            o1[6] += pa.y * vb.z; o1[7] += pa.y * vb.w;
        }
    }

    float inv0 = 1.0f / l0, inv1 = 1.0f / l1;
    long base0 = ((long)b * SEQ + q0 + r0) * HID + h * DH + tx * 8;
    long base1 = ((long)b * SEQ + q0 + r1) * HID + h * DH + tx * 8;
    *(float4*)(g_ctx + base0)     = make_float4(o0[0]*inv0, o0[1]*inv0, o0[2]*inv0, o0[3]*inv0);
    *(float4*)(g_ctx + base0 + 4) = make_float4(o0[4]*inv0, o0[5]*inv0, o0[6]*inv0, o0[7]*inv0);
    *(float4*)(g_ctx + base1)     = make_float4(o1[0]*inv1, o1[1]*inv1, o1[2]*inv1, o1[3]*inv1);
    *(float4*)(g_ctx + base1 + 4) = make_float4(o1[4]*inv1, o1[5]*inv1, o1[6]*inv1, o1[7]*inv1);
}

// ---------------- host launcher ---------------------------------------------
extern "C" void kernel_launch(void* const* d_in, const int* in_sizes, int n_in,
                              void* d_out, int out_size)
{
    const float* x   = (const float*)d_in[0];
    const float* bw  = (const float*)d_in[1];
    const float* sw  = (const float*)d_in[2];
    const float* sc  = (const float*)d_in[3];
    const float* grd = (const float*)d_in[4];
    const float* R   = (const float*)d_in[5];
    const float* ow  = (const float*)d_in[6];
    const float* ob  = (const float*)d_in[7];
    float* out = (float*)d_out;

    float *pA, *pB, *pqkv, *pctx;
    cudaGetSymbolAddress((void**)&pA,   g_A);
    cudaGetSymbolAddress((void**)&pB,   g_Bmat);
    cudaGetSymbolAddress((void**)&pqkv, g_qkv);
    cudaGetSymbolAddress((void**)&pctx, g_ctx);

    // 1. weights concat (+scaler)
    prep_w<<<(OUT3 * HID) / 256, 256>>>(bw, sw, sc);
    // 2. activations concat (silu + b-splines)
    prep_a<<<(NTOK * HID) / 256, 256>>>(x, grd);
    // 3. fused KAN GEMM: qkv = A * Bmat^T   (4096 x 3072 x 9216)
    gemm_nt<<<dim3(OUT3 / 128, NTOK / 128, 1), 256>>>(
        pA, pB, pqkv, KDIM, KDIM, KDIM, OUT3, nullptr);
    // 4. rotation (q,k) + v extraction
    rotqkv<<<dim3(BHN, SEQ / 64), 256>>>(R);
    // 5. flash attention -> ctx in (n, hid) layout
    flash_attn<<<dim3(SEQ / QT, BHN), 256>>>();
    // 6. out = ctx * out_w^T + out_b   (4096 x 1024 x 1024)
    gemm_nt<<<dim3(HID / 128, NTOK / 128, 1), 256>>>(
        pctx, ow, out, HID, HID, HID, HID, ob);
}

// round 5
// speedup vs baseline: 1.8329x; 1.8329x over previous
#include <cuda_runtime.h>
#include <cuda_bf16.h>
#include <math.h>
#include <stdint.h>

// Problem constants
#define HID   1024
#define NTOK  4096          // B*S
#define KDIM  9216          // 1024 silu + 8192 spline bases
#define K3    27648         // 3*KDIM (hi|lo|hi split along K)
#define OUT3  3072
#define SEQ   2048
#define BHN   32
#define DH    64
#define QT    64
#define KT    32

// GEMM tiling
#define BM 128
#define BN 128
#define BK 64
#define NT (K3/BK)          // 432 k-tiles
#define STG_BYTES 32768     // A 16KB + B 16KB per stage
#define SM_B_OFF  16384
#define NSTG 3

// ---------------- scratch (static __device__, no allocations) ----------------
__device__ __align__(16) __nv_bfloat16 g_Abf[(long)NTOK * K3];  // 226 MB
__device__ __align__(16) __nv_bfloat16 g_Bbf[(long)OUT3 * K3];  // 170 MB
__device__ __align__(16) float g_qkv [(long)NTOK * OUT3];
__device__ __align__(16) float g_qr  [(long)BHN * SEQ * DH];
__device__ __align__(16) float g_kr  [(long)BHN * SEQ * DH];
__device__ __align__(16) float g_vg  [(long)BHN * SEQ * DH];
__device__ __align__(16) float g_ctx [(long)NTOK * HID];

__device__ __forceinline__ uint32_t smem_u32(const void* p) {
    uint32_t a;
    asm("{ .reg .u64 t; cvta.to.shared.u64 t, %1; cvt.u32.u64 %0, t; }"
        : "=r"(a) : "l"(p));
    return a;
}
#define CP_ASYNC16(smaddr, gptr) \
    asm volatile("cp.async.cg.shared.global [%0], [%1], 16;" :: "r"(smaddr), "l"(gptr))
#define CP_COMMIT() asm volatile("cp.async.commit_group;")
#define CP_WAIT1()  asm volatile("cp.async.wait_group 1;")
#define LDSM_X4(r0,r1,r2,r3,addr) \
    asm volatile("ldmatrix.sync.aligned.m8n8.x4.shared.b16 {%0,%1,%2,%3}, [%4];" \
        : "=r"(r0),"=r"(r1),"=r"(r2),"=r"(r3) : "r"(addr))
#define HMMA(d, a, b0v, b1v) \
    asm volatile("mma.sync.aligned.m16n8k16.row.col.f32.bf16.bf16.f32 " \
        "{%0,%1,%2,%3}, {%4,%5,%6,%7}, {%8,%9}, {%0,%1,%2,%3};" \
        : "+f"(d[0]),"+f"(d[1]),"+f"(d[2]),"+f"(d[3]) \
        : "r"(a[0]),"r"(a[1]),"r"(a[2]),"r"(a[3]), "r"(b0v),"r"(b1v))

// ---------------- prep: Bbf = [hi | hi | lo] of [bw | sw*sc] -----------------
__global__ void prep_w(const float* __restrict__ bw,
                       const float* __restrict__ sw,
                       const float* __restrict__ sc)
{
    long i = (long)blockIdx.x * 256 + threadIdx.x;
    if (i >= (long)OUT3 * HID) return;
    int in = (int)(i & 1023);
    float s = sc[i];
    long rb = (long)(i >> 10) * K3;
    float v = bw[i];
    __nv_bfloat16 h = __float2bfloat16_rn(v);
    __nv_bfloat16 l = __float2bfloat16_rn(v - __bfloat162float(h));
    g_Bbf[rb + in] = h;
    g_Bbf[rb + KDIM + in] = h;
    g_Bbf[rb + 2*KDIM + in] = l;
    __nv_bfloat16 h8[8], l8[8];
#pragma unroll
    for (int j = 0; j < 8; j++) {
        float w = sw[i * 8 + j] * s;
        h8[j] = __float2bfloat16_rn(w);
        l8[j] = __float2bfloat16_rn(w - __bfloat162float(h8[j]));
    }
    long c = rb + HID + (long)in * 8;
    *(uint4*)&g_Bbf[c]          = *(uint4*)h8;
    *(uint4*)&g_Bbf[c + KDIM]   = *(uint4*)h8;
    *(uint4*)&g_Bbf[c + 2*KDIM] = *(uint4*)l8;
}

// ---------------- prep: Abf = [hi | lo | hi] of [silu(x) | b_splines(x)] ----
__global__ void prep_a(const float* __restrict__ x,
                       const float* __restrict__ grid)
{
    long i = (long)blockIdx.x * 256 + threadIdx.x;
    if (i >= (long)NTOK * HID) return;
    int in = (int)(i & 1023);
    float xv = x[i];
    long ra = (long)(i >> 10) * K3;
    float sv = xv / (1.0f + expf(-xv));
    __nv_bfloat16 h = __float2bfloat16_rn(sv);
    __nv_bfloat16 l = __float2bfloat16_rn(sv - __bfloat162float(h));
    g_Abf[ra + in] = h;
    g_Abf[ra + KDIM + in] = l;
    g_Abf[ra + 2*KDIM + in] = h;
    float g[12];
#pragma unroll
    for (int t = 0; t < 12; t++) g[t] = grid[in * 12 + t];
    float bas[11];
#pragma unroll
    for (int j = 0; j < 11; j++)
        bas[j] = (xv >= g[j] && xv < g[j + 1]) ? 1.0f : 0.0f;
#pragma unroll
    for (int p = 1; p <= 3; p++) {
#pragma unroll
        for (int j = 0; j < 11 - p; j++) {
            bas[j] = (xv - g[j]) / (g[j + p] - g[j]) * bas[j]
                   + (g[j + p + 1] - xv) / (g[j + p + 1] - g[j + 1]) * bas[j + 1];
        }
    }
    __nv_bfloat16 h8[8], l8[8];
#pragma unroll
    for (int j = 0; j < 8; j++) {
        h8[j] = __float2bfloat16_rn(bas[j]);
        l8[j] = __float2bfloat16_rn(bas[j] - __bfloat162float(h8[j]));
    }
    long c = ra + HID + (long)in * 8;
    *(uint4*)&g_Abf[c]          = *(uint4*)h8;
    *(uint4*)&g_Abf[c + KDIM]   = *(uint4*)l8;
    *(uint4*)&g_Abf[c + 2*KDIM] = *(uint4*)h8;
}

// ---------------- HMMA KAN GEMM: qkv = Abf(4096xK3) * Bbf(3072xK3)^T --------
// CTA 128x128x64, 8 warps (2x4), warp 64x32, 3-stage cp.async pipeline.
// smem tile: 128 rows x 64 halves (128B), swizzle chunk16 ^= (row&7).
__global__ void __launch_bounds__(256, 1) kan_gemm_mma()
{
    extern __shared__ char smem[];
    const uint32_t sb = smem_u32(smem);
    const int tid = threadIdx.x;
    const int wid = tid >> 5;
    const int lane = tid & 31;
    const int m0 = blockIdx.y * BM;
    const int n0 = blockIdx.x * BN;
    const int wm = wid & 1;          // 0..1
    const int wn = wid >> 1;         // 0..3

    // loader mapping: 4 chunks per operand per thread
    const int r0 = tid >> 3;         // 0..31, +u*32
    const int c0 = tid & 7;          // 16B chunk in row
    const __nv_bfloat16* aG = g_Abf + (long)(m0 + r0) * K3 + c0 * 8;
    const __nv_bfloat16* bG = g_Bbf + (long)(n0 + r0) * K3 + c0 * 8;
    uint32_t sA[4], sB[4];
#pragma unroll
    for (int u = 0; u < 4; u++) {
        int row = r0 + u * 32;
        uint32_t off = row * 128 + ((c0 ^ (row & 7)) << 4);
        sA[u] = sb + off;
        sB[u] = sb + SM_B_OFF + off;
    }

    // prefetch stages 0,1
#pragma unroll
    for (int s = 0; s < 2; s++) {
        long co = (long)s * BK;
        uint32_t bo = s * STG_BYTES;
#pragma unroll
        for (int u = 0; u < 4; u++) {
            CP_ASYNC16(sA[u] + bo, aG + (long)u * 32 * K3 + co);
            CP_ASYNC16(sB[u] + bo, bG + (long)u * 32 * K3 + co);
        }
        CP_COMMIT();
    }

    float acc[4][4][4];
#pragma unroll
    for (int mi = 0; mi < 4; mi++)
#pragma unroll
        for (int ni = 0; ni < 4; ni++)
#pragma unroll
            for (int r = 0; r < 4; r++) acc[mi][ni][r] = 0.0f;

    // per-lane ldmatrix addressing
    const int lrow = lane & 15;           // row within 16-row frag
    const int lchk = lane >> 4;           // 0/1 -> k halves 0-7 / 8-15
    const int lswz = lane & 7;            // swizzle XOR operand
    // A frag base offsets (row part), per mi
    uint32_t aRow[4], bRow[2];
#pragma unroll
    for (int mi = 0; mi < 4; mi++)
        aRow[mi] = (uint32_t)((wm * 64 + mi * 16 + lrow) * 128);
#pragma unroll
    for (int bi = 0; bi < 2; bi++)
        bRow[bi] = (uint32_t)(SM_B_OFF + (wn * 32 + bi * 16 + lrow) * 128);

    for (int t = 0; t < NT; t++) {
        CP_WAIT1();
        __syncthreads();
        // issue stage t+2
        if (t + 2 < NT) {
            long co = (long)(t + 2) * BK;
            uint32_t bo = ((t + 2) % NSTG) * STG_BYTES;
#pragma unroll
            for (int u = 0; u < 4; u++) {
                CP_ASYNC16(sA[u] + bo, aG + (long)u * 32 * K3 + co);
                CP_ASYNC16(sB[u] + bo, bG + (long)u * 32 * K3 + co);
            }
        }
        CP_COMMIT();

        const uint32_t stb = sb + (t % NSTG) * STG_BYTES;
#pragma unroll
        for (int kk = 0; kk < 4; kk++) {
            const uint32_t chq = (uint32_t)(kk * 2 + lchk);
            uint32_t a[4][4], b[2][4];
#pragma unroll
            for (int mi = 0; mi < 4; mi++) {
                uint32_t ad = stb + aRow[mi] + (((chq) ^ lswz) << 4);
                LDSM_X4(a[mi][0], a[mi][1], a[mi][2], a[mi][3], ad);
            }
#pragma unroll
            for (int bi = 0; bi < 2; bi++) {
                uint32_t bd = stb + bRow[bi] + (((chq) ^ lswz) << 4);
                LDSM_X4(b[bi][0], b[bi][1], b[bi][2], b[bi][3], bd);
            }
#pragma unroll
            for (int mi = 0; mi < 4; mi++) {
                HMMA(acc[mi][0], a[mi], b[0][0], b[0][2]);
                HMMA(acc[mi][1], a[mi], b[0][1], b[0][3]);
                HMMA(acc[mi][2], a[mi], b[1][0], b[1][2]);
                HMMA(acc[mi][3], a[mi], b[1][1], b[1][3]);
            }
        }
    }

    // epilogue
    const int erow = lane >> 2;
    const int ecol = (lane & 3) * 2;
#pragma unroll
    for (int mi = 0; mi < 4; mi++) {
        long row = m0 + wm * 64 + mi * 16 + erow;
#pragma unroll
        for (int ni = 0; ni < 4; ni++) {
            int col = n0 + wn * 32 + ni * 8 + ecol;
            *(float2*)&g_qkv[row * OUT3 + col] =
                make_float2(acc[mi][ni][0], acc[mi][ni][1]);
            *(float2*)&g_qkv[(row + 8) * OUT3 + col] =
                make_float2(acc[mi][ni][2], acc[mi][ni][3]);
        }
    }
}

// ---------------- fp32 NT GEMM (out-proj): C = A*B^T + bias -----------------
__global__ void __launch_bounds__(256) gemm_nt(
    const float* __restrict__ A, const float* __restrict__ B, float* __restrict__ C,
    int K, int lda, int ldb, int ldc, const float* __restrict__ bias)
{
    const int brow = blockIdx.y * 128;
    const int bcol = blockIdx.x * 128;
    __shared__ float As[2][16][132];
    __shared__ float Bs[2][16][132];
    const int tid = threadIdx.x;
    const int tx = tid & 15, ty = tid >> 4;
    const int r_0 = tid >> 1, kq_0 = (tid & 1) * 4, kq_1 = kq_0 + 8;
    const float* Arow0 = A + (long)(brow + r_0) * lda;
    const float* Brow0 = B + (long)(bcol + r_0) * ldb;
    float acc[8][8];
#pragma unroll
    for (int i = 0; i < 8; i++)
#pragma unroll
        for (int j = 0; j < 8; j++) acc[i][j] = 0.0f;
    const int ntile = K / 16;
    {
        float4 va0 = *(const float4*)(Arow0 + kq_0);
        float4 va1 = *(const float4*)(Arow0 + kq_1);
        float4 vb0 = *(const float4*)(Brow0 + kq_0);
        float4 vb1 = *(const float4*)(Brow0 + kq_1);
        As[0][kq_0+0][r_0]=va0.x; As[0][kq_0+1][r_0]=va0.y; As[0][kq_0+2][r_0]=va0.z; As[0][kq_0+3][r_0]=va0.w;
        As[0][kq_1+0][r_0]=va1.x; As[0][kq_1+1][r_0]=va1.y; As[0][kq_1+2][r_0]=va1.z; As[0][kq_1+3][r_0]=va1.w;
        Bs[0][kq_0+0][r_0]=vb0.x; Bs[0][kq_0+1][r_0]=vb0.y; Bs[0][kq_0+2][r_0]=vb0.z; Bs[0][kq_0+3][r_0]=vb0.w;
        Bs[0][kq_1+0][r_0]=vb1.x; Bs[0][kq_1+1][r_0]=vb1.y; Bs[0][kq_1+2][r_0]=vb1.z; Bs[0][kq_1+3][r_0]=vb1.w;
    }
    __syncthreads();
    for (int t = 0; t < ntile; t++) {
        const int cur = t & 1, nxt = cur ^ 1;
        float4 va0, va1, vb0, vb1;
        const bool more = (t + 1) < ntile;
        if (more) {
            int ko = (t + 1) * 16;
            va0 = *(const float4*)(Arow0 + ko + kq_0);
            va1 = *(const float4*)(Arow0 + ko + kq_1);
            vb0 = *(const float4*)(Brow0 + ko + kq_0);
            vb1 = *(const float4*)(Brow0 + ko + kq_1);
        }
#pragma unroll
        for (int kk = 0; kk < 16; kk++) {
            float ra[8], rb[8];
#pragma unroll
            for (int i = 0; i < 8; i++) ra[i] = As[cur][kk][ty * 8 + i];
#pragma unroll
            for (int j = 0; j < 8; j++) rb[j] = Bs[cur][kk][tx * 8 + j];
#pragma unroll
            for (int i = 0; i < 8; i++)
#pragma unroll
                for (int j = 0; j < 8; j++) acc[i][j] += ra[i] * rb[j];
        }
        if (more) {
            As[nxt][kq_0+0][r_0]=va0.x; As[nxt][kq_0+1][r_0]=va0.y; As[nxt][kq_0+2][r_0]=va0.z; As[nxt][kq_0+3][r_0]=va0.w;
            As[nxt][kq_1+0][r_0]=va1.x; As[nxt][kq_1+1][r_0]=va1.y; As[nxt][kq_1+2][r_0]=va1.z; As[nxt][kq_1+3][r_0]=va1.w;
            Bs[nxt][kq_0+0][r_0]=vb0.x; Bs[nxt][kq_0+1][r_0]=vb0.y; Bs[nxt][kq_0+2][r_0]=vb0.z; Bs[nxt][kq_0+3][r_0]=vb0.w;
            Bs[nxt][kq_1+0][r_0]=vb1.x; Bs[nxt][kq_1+1][r_0]=vb1.y; Bs[nxt][kq_1+2][r_0]=vb1.z; Bs[nxt][kq_1+3][r_0]=vb1.w;
        }
        __syncthreads();
    }
#pragma unroll
    for (int i = 0; i < 8; i++) {
        long row = brow + ty * 8 + i;
#pragma unroll
        for (int j = 0; j < 8; j++) {
            int col = bcol + tx * 8 + j;
            float v = acc[i][j];
            if (bias) v += bias[col];
            C[row * ldc + col] = v;
        }
    }
}

// ---------------- rotate q,k by R + copy v -----------------------------------
__global__ void __launch_bounds__(256) rotqkv(const float* __restrict__ R)
{
    const int bh = blockIdx.x;
    const int s0 = blockIdx.y * 64;
    const int b = bh >> 4, h = bh & 15;
    __shared__ float RsT[64][65];
    __shared__ float T[64][64];
    const int tid = threadIdx.x;
    for (int i = tid; i < 4096; i += 256) {
        int m = i >> 6, d = i & 63;
        RsT[d][m] = R[i];
    }
    for (int i = tid; i < 4096; i += 256) {
        int t = i >> 6, d = i & 63;
        long n = (long)(b * SEQ + s0 + t);
        const float* base = g_qkv + n * OUT3 + h * 192;
        T[t][d] = base[d];
        g_vg[((long)bh * SEQ + s0 + t) * DH + d] = base[128 + d];
    }
    __syncthreads();
    for (int i = tid; i < 4096; i += 256) {
        int t = i >> 6, m = i & 63;
        float sum = 0.0f;
#pragma unroll
        for (int d = 0; d < 64; d++) sum += T[t][d] * RsT[d][m];
        g_qr[((long)bh * SEQ + s0 + t) * DH + m] = sum;
    }
    __syncthreads();
    for (int i = tid; i < 4096; i += 256) {
        int t = i >> 6, d = i & 63;
        long n = (long)(b * SEQ + s0 + t);
        T[t][d] = g_qkv[n * OUT3 + h * 192 + 64 + d];
    }
    __syncthreads();
    for (int i = tid; i < 4096; i += 256) {
        int t = i >> 6, m = i & 63;
        float sum = 0.0f;
#pragma unroll
        for (int d = 0; d < 64; d++) sum += T[t][d] * RsT[d][m];
        g_kr[((long)bh * SEQ + s0 + t) * DH + m] = sum;
    }
}

// ---------------- flash attention: ctx = softmax(qr krT / 8) v --------------
__global__ void __launch_bounds__(256) flash_attn()
{
    const int bh = blockIdx.y;
    const int q0 = blockIdx.x * QT;
    const int b = bh >> 4, h = bh & 15;
    __shared__ float Qst[DH][QT];
    __shared__ float Kst[DH][KT];
    __shared__ float Vs [KT][DH];
    __shared__ float Pst[KT][QT + 2];
    const int tid = threadIdx.x;
    const int tx = tid & 7;
    const int ty = tid >> 3;
    const int r0 = ty * 2, r1 = r0 + 1;
#pragma unroll
    for (int u = 0; u < 4; u++) {
        int e = tid + u * 256;
        int q = e >> 4;
        int d4 = (e & 15) * 4;
        float4 v = *(const float4*)(g_qr + ((long)bh * SEQ + q0 + q) * DH + d4);
        Qst[d4+0][q]=v.x; Qst[d4+1][q]=v.y; Qst[d4+2][q]=v.z; Qst[d4+3][q]=v.w;
    }
    float m0 = -1e30f, m1 = -1e30f, l0 = 0.f, l1 = 0.f;
    float o0[8], o1[8];
#pragma unroll
    for (int u = 0; u < 8; u++) { o0[u] = 0.f; o1[u] = 0.f; }
    for (int kt = 0; kt < SEQ; kt += KT) {
        __syncthreads();
#pragma unroll
        for (int u = 0; u < 2; u++) {
            int e = tid + u * 256;
            int n = e >> 4;
            int d4 = (e & 15) * 4;
            float4 kv = *(const float4*)(g_kr + ((long)bh * SEQ + kt + n) * DH + d4);
            Kst[d4+0][n]=kv.x; Kst[d4+1][n]=kv.y; Kst[d4+2][n]=kv.z; Kst[d4+3][n]=kv.w;
            float4 vv = *(const float4*)(g_vg + ((long)bh * SEQ + kt + n) * DH + d4);
            *(float4*)&Vs[n][d4] = vv;
        }
        __syncthreads();
        float s0[4], s1[4];
#pragma unroll
        for (int c = 0; c < 4; c++) { s0[c] = 0.f; s1[c] = 0.f; }
#pragma unroll 8
        for (int kk = 0; kk < DH; kk++) {
            float2 qa = *(const float2*)&Qst[kk][r0];
            float4 kb = *(const float4*)&Kst[kk][tx * 4];
            s0[0]+=qa.x*kb.x; s0[1]+=qa.x*kb.y; s0[2]+=qa.x*kb.z; s0[3]+=qa.x*kb.w;
            s1[0]+=qa.y*kb.x; s1[1]+=qa.y*kb.y; s1[2]+=qa.y*kb.z; s1[3]+=qa.y*kb.w;
        }
        float tm0 = -1e30f, tm1 = -1e30f;
#pragma unroll
        for (int c = 0; c < 4; c++) {
            s0[c] *= 0.125f; s1[c] *= 0.125f;
            tm0 = fmaxf(tm0, s0[c]); tm1 = fmaxf(tm1, s1[c]);
        }
#pragma unroll
        for (int o = 1; o < 8; o <<= 1) {
            tm0 = fmaxf(tm0, __shfl_xor_sync(0xffffffffu, tm0, o));
            tm1 = fmaxf(tm1, __shfl_xor_sync(0xffffffffu, tm1, o));
        }
        float nm0 = fmaxf(m0, tm0), nm1 = fmaxf(m1, tm1);
        float c0 = __expf(m0 - nm0), c1 = __expf(m1 - nm1);
        m0 = nm0; m1 = nm1;
        float ts0 = 0.f, ts1 = 0.f;
        float p0[4], p1[4];
#pragma unroll
        for (int c = 0; c < 4; c++) {
            p0[c] = __expf(s0[c] - nm0); ts0 += p0[c];
            p1[c] = __expf(s1[c] - nm1); ts1 += p1[c];
        }
#pragma unroll
        for (int o = 1; o < 8; o <<= 1) {
            ts0 += __shfl_xor_sync(0xffffffffu, ts0, o);
            ts1 += __shfl_xor_sync(0xffffffffu, ts1, o);
        }
        l0 = l0 * c0 + ts0;
        l1 = l1 * c1 + ts1;
#pragma unroll
        for (int u = 0; u < 8; u++) { o0[u] *= c0; o1[u] *= c1; }
#pragma unroll
        for (int c = 0; c < 4; c++) {
            Pst[tx * 4 + c][r0] = p0[c];
            Pst[tx * 4 + c][r1] = p1[c];
        }
        __syncthreads();
#pragma unroll 4
        for (int j = 0; j < KT; j++) {
            float2 pa = *(const float2*)&Pst[j][r0];
            float4 va = *(const float4*)&Vs[j][tx * 8];
            float4 vb = *(const float4*)&Vs[j][tx * 8 + 4];
            o0[0]+=pa.x*va.x; o0[1]+=pa.x*va.y; o0[2]+=pa.x*va.z; o0[3]+=pa.x*va.w;
            o0[4]+=pa.x*vb.x; o0[5]+=pa.x*vb.y; o0[6]+=pa.x*vb.z; o0[7]+=pa.x*vb.w;
            o1[0]+=pa.y*va.x; o1[1]+=pa.y*va.y; o1[2]+=pa.y*va.z; o1[3]+=pa.y*va.w;
            o1[4]+=pa.y*vb.x; o1[5]+=pa.y*vb.y; o1[6]+=pa.y*vb.z; o1[7]+=pa.y*vb.w;
        }
    }
    float inv0 = 1.0f / l0, inv1 = 1.0f / l1;
    long base0 = ((long)b * SEQ + q0 + r0) * HID + h * DH + tx * 8;
    long base1 = ((long)b * SEQ + q0 + r1) * HID + h * DH + tx * 8;
    *(float4*)(g_ctx + base0)     = make_float4(o0[0]*inv0, o0[1]*inv0, o0[2]*inv0, o0[3]*inv0);
    *(float4*)(g_ctx + base0 + 4) = make_float4(o0[4]*inv0, o0[5]*inv0, o0[6]*inv0, o0[7]*inv0);
    *(float4*)(g_ctx + base1)     = make_float4(o1[0]*inv1, o1[1]*inv1, o1[2]*inv1, o1[3]*inv1);
    *(float4*)(g_ctx + base1 + 4) = make_float4(o1[4]*inv1, o1[5]*inv1, o1[6]*inv1, o1[7]*inv1);
}

// ---------------- host launcher ---------------------------------------------
extern "C" void kernel_launch(void* const* d_in, const int* in_sizes, int n_in,
                              void* d_out, int out_size)
{
    const float* x   = (const float*)d_in[0];
    const float* bw  = (const float*)d_in[1];
    const float* sw  = (const float*)d_in[2];
    const float* sc  = (const float*)d_in[3];
    const float* grd = (const float*)d_in[4];
    const float* R   = (const float*)d_in[5];
    const float* ow  = (const float*)d_in[6];
    const float* ob  = (const float*)d_in[7];
    float* out = (float*)d_out;

    float* pctx;
    cudaGetSymbolAddress((void**)&pctx, g_ctx);

    cudaFuncSetAttribute(kan_gemm_mma, cudaFuncAttributeMaxDynamicSharedMemorySize,
                         NSTG * STG_BYTES);

    // 1. weights: bf16 hi/lo split concat
    prep_w<<<(OUT3 * HID) / 256, 256>>>(bw, sw, sc);
    // 2. activations: silu + b-splines, bf16 hi/lo split concat
    prep_a<<<(NTOK * HID) / 256, 256>>>(x, grd);
    // 3. fused KAN GEMM via HMMA: qkv = Abf * Bbf^T  (4096 x 3072 x 27648 bf16)
    kan_gemm_mma<<<dim3(OUT3 / BN, NTOK / BM), 256, NSTG * STG_BYTES>>>();
    // 4. rotation (q,k) + v extraction
    rotqkv<<<dim3(BHN, SEQ / 64), 256>>>(R);
    // 5. flash attention -> ctx
    flash_attn<<<dim3(SEQ / QT, BHN), 256>>>();
    // 6. out = ctx * out_w^T + out_b
    gemm_nt<<<dim3(HID / 128, NTOK / 128), 256>>>(
        pctx, ow, out, HID, HID, HID, HID, ob);
}